// round 1
// baseline (speedup 1.0000x reference)
#include <cuda_runtime.h>
#include <cstddef>

// Scratch: f1t [2][4096][256] at offset 0 (2,097,152 floats)
//          f2t [2][5440][256] at offset 2,097,152 (2,785,280 floats)
// total 4,882,432 floats = 19.5 MB
#define F1T_OFF   ((size_t)0)
#define F2T_OFF   ((size_t)2097152)
#define F2T_BSTRIDE ((size_t)1392640)   // 5440*256
__device__ float g_scratch[4882432];

// ---------------------------------------------------------------------------
// Transpose [C=256, P] -> [P, 256] per batch (blockIdx.z = batch)
// P divisible by 32 for all tensors here.
// ---------------------------------------------------------------------------
__global__ void transpose_kernel(const float* __restrict__ src,
                                 size_t dstBase, size_t dstBatchStride, int P) {
    __shared__ float tile[32][33];
    const int bz = blockIdx.z;
    const float* s = src + (size_t)bz * 256 * P;
    float* d = g_scratch + dstBase + (size_t)bz * dstBatchStride;
    const int pBase = blockIdx.x * 32;
    const int cBase = blockIdx.y * 32;
    const int tx = threadIdx.x, ty = threadIdx.y;  // 32 x 8
#pragma unroll
    for (int k = 0; k < 4; k++)
        tile[ty + 8 * k][tx] = s[(size_t)(cBase + ty + 8 * k) * P + pBase + tx];
    __syncthreads();
#pragma unroll
    for (int k = 0; k < 4; k++)
        d[(size_t)(pBase + ty + 8 * k) * 256 + cBase + tx] = tile[tx][ty + 8 * k];
}

// ---------------------------------------------------------------------------
// Main correlation kernel. One block = 8 consecutive pixels (same row).
// 256 threads = 8 warps. Per (pixel, level): 100 integer-grid dot products
// (each warp: one point, lanes cover 8 channels each, shuffle-reduce),
// then 81 bilinear combinations written to out.
// ---------------------------------------------------------------------------
__global__ __launch_bounds__(256) void corr_kernel(const float* __restrict__ coords,
                                                   float* __restrict__ out) {
    __shared__ float f1s[8 * 256];
    __shared__ float dots[8][100];
    __shared__ float s_cx[8], s_cy[8];

    const int tid  = threadIdx.x;
    const int pix0 = blockIdx.x * 8;          // global linear pixel (b*4096 + h*64 + w)
    const int b    = pix0 >> 12;
    const int hw   = pix0 & 4095;

    // Load 8 f1 vectors (contiguous in f1t) into smem
    const float* f1t = g_scratch + F1T_OFF + (size_t)pix0 * 256;
#pragma unroll
    for (int i = tid; i < 2048; i += 256) f1s[i] = f1t[i];
    if (tid < 8) {
        s_cx[tid] = coords[(size_t)b * 8192 + hw + tid];
        s_cy[tid] = coords[(size_t)b * 8192 + 4096 + hw + tid];
    }
    __syncthreads();

    const int warp = tid >> 5;
    const int lane = tid & 31;
    const int lvl_base[4] = {0, 4096, 5120, 5376};

#pragma unroll 1
    for (int lvl = 0; lvl < 4; lvl++) {
        const int W2 = 64 >> lvl;
        const float scale = 1.0f / (float)(1 << lvl);
        const float* f2b = g_scratch + F2T_OFF + (size_t)b * F2T_BSTRIDE +
                           (size_t)lvl_base[lvl] * 256;

#pragma unroll 1
        for (int px = 0; px < 8; px++) {
            const float x = s_cx[px] * scale;
            const float y = s_cy[px] * scale;
            const int x0 = (int)floorf(x);
            const int y0 = (int)floorf(y);

            // this lane's 8-channel slice of f1 for this pixel
            const float4 ra = *(const float4*)&f1s[px * 256 + lane * 8];
            const float4 rb = *(const float4*)&f1s[px * 256 + lane * 8 + 4];

            for (int pt = warp; pt < 100; pt += 8) {
                const int gi = pt / 10;
                const int gj = pt - gi * 10;
                const int gx = x0 - 4 + gj;
                const int gy = y0 - 4 + gi;
                float v = 0.0f;
                if ((unsigned)gx < (unsigned)W2 && (unsigned)gy < (unsigned)W2) {
                    const float4* p =
                        (const float4*)(f2b + ((size_t)(gy * W2 + gx) << 8) + lane * 8);
                    const float4 a = p[0];
                    const float4 c = p[1];
                    v = a.x * ra.x + a.y * ra.y + a.z * ra.z + a.w * ra.w +
                        c.x * rb.x + c.y * rb.y + c.z * rb.z + c.w * rb.w;
                }
                v += __shfl_xor_sync(0xffffffffu, v, 16);
                v += __shfl_xor_sync(0xffffffffu, v, 8);
                v += __shfl_xor_sync(0xffffffffu, v, 4);
                v += __shfl_xor_sync(0xffffffffu, v, 2);
                v += __shfl_xor_sync(0xffffffffu, v, 1);
                if (lane == 0) dots[px][pt] = v;
            }
        }
        __syncthreads();

        // 81 offsets x 8 pixels = 648 outputs
        for (int e = tid; e < 648; e += 256) {
            const int k  = e >> 3;
            const int px = e & 7;
            const int oi = k / 9;
            const int oj = k - oi * 9;
            const float x = s_cx[px] * scale;
            const float y = s_cy[px] * scale;
            const float fx = x - floorf(x);
            const float fy = y - floorf(y);
            const float w00 = (1.0f - fx) * (1.0f - fy);
            const float w10 = fx * (1.0f - fy);
            const float w01 = (1.0f - fx) * fy;
            const float w11 = fx * fy;
            const int base = oi * 10 + oj;
            const float val = w00 * dots[px][base]      + w10 * dots[px][base + 1] +
                              w01 * dots[px][base + 10] + w11 * dots[px][base + 11];
            out[(size_t)(b * 324 + lvl * 81 + k) * 4096 + hw + px] = val * 0.0625f;
        }
        __syncthreads();
    }
}

// ---------------------------------------------------------------------------
// Inputs (metadata order): fmap1, fmap2_0, fmap2_1, fmap2_2, fmap2_3, coords
// Output: [2, 324, 64, 64] float32
// ---------------------------------------------------------------------------
extern "C" void kernel_launch(void* const* d_in, const int* in_sizes, int n_in,
                              void* d_out, int out_size) {
    const float* f1     = (const float*)d_in[0];
    const float* f2_0   = (const float*)d_in[1];
    const float* f2_1   = (const float*)d_in[2];
    const float* f2_2   = (const float*)d_in[3];
    const float* f2_3   = (const float*)d_in[4];
    const float* coords = (const float*)d_in[5];
    float* out = (float*)d_out;

    dim3 tb(32, 8);
    // f1: [2,256,4096] -> f1t
    transpose_kernel<<<dim3(4096 / 32, 8, 2), tb>>>(f1, F1T_OFF, (size_t)1048576, 4096);
    // f2 levels -> f2t (level bases 0, 4096, 5120, 5376 pixels)
    transpose_kernel<<<dim3(4096 / 32, 8, 2), tb>>>(f2_0, F2T_OFF + (size_t)0    * 256, F2T_BSTRIDE, 4096);
    transpose_kernel<<<dim3(1024 / 32, 8, 2), tb>>>(f2_1, F2T_OFF + (size_t)4096 * 256, F2T_BSTRIDE, 1024);
    transpose_kernel<<<dim3(256  / 32, 8, 2), tb>>>(f2_2, F2T_OFF + (size_t)5120 * 256, F2T_BSTRIDE, 256);
    transpose_kernel<<<dim3(64   / 32, 8, 2), tb>>>(f2_3, F2T_OFF + (size_t)5376 * 256, F2T_BSTRIDE, 64);

    corr_kernel<<<1024, 256>>>(coords, out);
}

// round 3
// speedup vs baseline: 2.2792x; 2.2792x over previous
#include <cuda_runtime.h>
#include <cuda_fp16.h>
#include <cstdint>
#include <cstddef>

// ---------------------------------------------------------------------------
// Scratch:
//   g_fh: f1h [2][4096][256] fp16 at 0; f2h [2][5504][256] fp16 at 2,097,152
//         (f2 level row bases 0,4096,5120,5376; rows 5440..5503 stay zero)
//   g_corr: [2][4096][5504] fp32
// ---------------------------------------------------------------------------
#define F1H_OFF ((size_t)0)
#define F2H_OFF ((size_t)2097152)
#define F2_BSTRIDE ((size_t)1409024)   // 5504*256
#define CORR_COLS 5504
__device__ __half g_fh[4915200];
__device__ float  g_corr[45088768];

__device__ __forceinline__ uint32_t smem_u32(const void* p) {
    uint32_t a;
    asm("{ .reg .u64 t; cvta.to.shared.u64 t, %1; cvt.u32.u64 %0, t; }"
        : "=r"(a) : "l"(p));
    return a;
}

// ---------------------------------------------------------------------------
// Transpose+convert [C=256,P] fp32 -> [P,256] fp16
// ---------------------------------------------------------------------------
__global__ void tconv_kernel(const float* __restrict__ src, size_t dstOff,
                             size_t dstBatchStride, int P) {
    __shared__ float tile[32][33];
    const int bz = blockIdx.z;
    const float* s = src + (size_t)bz * 256 * P;
    __half* d = g_fh + dstOff + (size_t)bz * dstBatchStride;
    const int pBase = blockIdx.x * 32, cBase = blockIdx.y * 32;
    const int tx = threadIdx.x, ty = threadIdx.y;
#pragma unroll
    for (int k = 0; k < 4; k++)
        tile[ty + 8 * k][tx] = s[(size_t)(cBase + ty + 8 * k) * P + pBase + tx];
    __syncthreads();
#pragma unroll
    for (int k = 0; k < 4; k++)
        d[(size_t)(pBase + ty + 8 * k) * 256 + cBase + tx] = __float2half(tile[tx][ty + 8 * k]);
}

// ---------------------------------------------------------------------------
// GEMM via mma.sync m16n8k16 (HMMA). Tile 128(M) x 128(N), K=256 in smem.
// 8 warps: 4 in M x 2 in N; warp tile 32x64.
// Smem rows padded to 264 halves (528B: stride == 16 mod 128 -> ldmatrix
// conflict-free).
// ---------------------------------------------------------------------------
#define AROW 264
#define GEMM_SMEM (2 * 128 * AROW * 2)   // 135168 bytes

__device__ __forceinline__ void ldsm_x4(uint32_t (&r)[4], uint32_t addr) {
    asm volatile("ldmatrix.sync.aligned.m8n8.x4.shared.b16 {%0,%1,%2,%3}, [%4];"
                 : "=r"(r[0]), "=r"(r[1]), "=r"(r[2]), "=r"(r[3]) : "r"(addr));
}
__device__ __forceinline__ void mma16816(float (&d)[4], const uint32_t (&a)[4],
                                         uint32_t b0, uint32_t b1) {
    asm volatile(
        "mma.sync.aligned.m16n8k16.row.col.f32.f16.f16.f32 "
        "{%0,%1,%2,%3},{%4,%5,%6,%7},{%8,%9},{%0,%1,%2,%3};"
        : "+f"(d[0]), "+f"(d[1]), "+f"(d[2]), "+f"(d[3])
        : "r"(a[0]), "r"(a[1]), "r"(a[2]), "r"(a[3]), "r"(b0), "r"(b1));
}

__global__ void __launch_bounds__(256, 1) gemm_kernel() {
    extern __shared__ __half sm[];
    __half* sA = sm;
    __half* sB = sm + 128 * AROW;

    const int tid = threadIdx.x, warp = tid >> 5, lane = tid & 31;
    const int nt = blockIdx.x, mt = blockIdx.y, b = blockIdx.z;

    const __half* A = g_fh + F1H_OFF + ((size_t)b * 4096 + (size_t)mt * 128) * 256;
    const __half* B = g_fh + F2H_OFF + (size_t)b * F2_BSTRIDE + (size_t)nt * 128 * 256;

    // Stage both 128x256 fp16 tiles (16B chunks, coalesced)
#pragma unroll
    for (int i = tid; i < 4096; i += 256) {
        const int r = i >> 5, c = i & 31;
        *(uint4*)&sA[r * AROW + c * 8] = *(const uint4*)(A + (size_t)r * 256 + c * 8);
        *(uint4*)&sB[r * AROW + c * 8] = *(const uint4*)(B + (size_t)r * 256 + c * 8);
    }
    __syncthreads();

    const int wm = (warp & 3) * 32;      // warp M offset in tile
    const int wn = (warp >> 2) * 64;     // warp N offset in tile
    const int row_in = lane & 7;
    const int mat = lane >> 3;           // which 8x8 matrix this lane addresses

    float acc[2][8][4];
#pragma unroll
    for (int mi = 0; mi < 2; mi++)
#pragma unroll
        for (int ni = 0; ni < 8; ni++)
#pragma unroll
            for (int j = 0; j < 4; j++) acc[mi][ni][j] = 0.0f;

    const uint32_t sA0 = smem_u32(sA);
    const uint32_t sB0 = smem_u32(sB);

#pragma unroll 4
    for (int kk = 0; kk < 256; kk += 16) {
        uint32_t af[2][4];
#pragma unroll
        for (int mi = 0; mi < 2; mi++) {
            // regs: (rows g,klo),(g+8,klo),(g,khi),(g+8,khi)
            const int row = wm + mi * 16 + (mat & 1) * 8 + row_in;
            const int col = kk + (mat >> 1) * 8;
            ldsm_x4(af[mi], sA0 + (uint32_t)(row * AROW + col) * 2);
        }
        uint32_t bf[4][4];
#pragma unroll
        for (int bi = 0; bi < 4; bi++) {
            // regs: (nblk0,klo),(nblk0,khi),(nblk1,klo),(nblk1,khi)
            const int nrow = wn + bi * 16 + (mat >> 1) * 8 + row_in;
            const int col = kk + (mat & 1) * 8;
            ldsm_x4(bf[bi], sB0 + (uint32_t)(nrow * AROW + col) * 2);
        }
#pragma unroll
        for (int mi = 0; mi < 2; mi++)
#pragma unroll
            for (int ni = 0; ni < 8; ni++) {
                const uint32_t* bb = bf[ni >> 1];
                if (ni & 1) mma16816(acc[mi][ni], af[mi], bb[2], bb[3]);
                else        mma16816(acc[mi][ni], af[mi], bb[0], bb[1]);
            }
    }

    // Store: c0,c1 at (row g, col 2tg+{0,1}); c2,c3 at row g+8
    const int g = lane >> 2, tg = lane & 3;
    float* crow = g_corr + ((size_t)b * 4096 + (size_t)mt * 128) * CORR_COLS +
                  (size_t)nt * 128;
#pragma unroll
    for (int mi = 0; mi < 2; mi++) {
#pragma unroll
        for (int ni = 0; ni < 8; ni++) {
            const int rm = wm + mi * 16 + g;
            const int cn = wn + ni * 8 + tg * 2;
            *(float2*)(crow + (size_t)rm * CORR_COLS + cn) =
                make_float2(acc[mi][ni][0], acc[mi][ni][1]);
            *(float2*)(crow + (size_t)(rm + 8) * CORR_COLS + cn) =
                make_float2(acc[mi][ni][2], acc[mi][ni][3]);
        }
    }
}

// ---------------------------------------------------------------------------
// Gather: per (pixel, level) read 10x10 grid from g_corr, combine to 81 outs.
// One block = 8 consecutive pixels.
// ---------------------------------------------------------------------------
__global__ __launch_bounds__(256) void gather_kernel(const float* __restrict__ coords,
                                                     float* __restrict__ out) {
    __shared__ float dots[8][100];
    __shared__ float s_cx[8], s_cy[8];

    const int tid = threadIdx.x;
    const int pix0 = blockIdx.x * 8;
    const int b = pix0 >> 12;
    const int hw = pix0 & 4095;

    if (tid < 8) {
        s_cx[tid] = coords[(size_t)b * 8192 + hw + tid];
        s_cy[tid] = coords[(size_t)b * 8192 + 4096 + hw + tid];
    }
    __syncthreads();

    const int lvl_base[4] = {0, 4096, 5120, 5376};

#pragma unroll 1
    for (int lvl = 0; lvl < 4; lvl++) {
        const int W2 = 64 >> lvl;
        const float scale = 1.0f / (float)(1 << lvl);
        const int lb = lvl_base[lvl];

        for (int e = tid; e < 1024; e += 256) {
            const int px = e >> 7;
            const int pt = e & 127;
            if (pt < 100) {
                const float x = s_cx[px] * scale;
                const float y = s_cy[px] * scale;
                const int x0 = (int)floorf(x);
                const int y0 = (int)floorf(y);
                const int gi = pt / 10;
                const int gj = pt - gi * 10;
                const int gx = x0 - 4 + gj;
                const int gy = y0 - 4 + gi;
                float v = 0.0f;
                if ((unsigned)gx < (unsigned)W2 && (unsigned)gy < (unsigned)W2)
                    v = g_corr[((size_t)b * 4096 + hw + px) * CORR_COLS + lb + gy * W2 + gx];
                dots[px][pt] = v;
            }
        }
        __syncthreads();

        for (int e = tid; e < 648; e += 256) {
            const int k = e >> 3;
            const int px = e & 7;
            const int oi = k / 9;
            const int oj = k - oi * 9;
            const float x = s_cx[px] * scale;
            const float y = s_cy[px] * scale;
            const float fx = x - floorf(x);
            const float fy = y - floorf(y);
            const float w00 = (1.0f - fx) * (1.0f - fy);
            const float w10 = fx * (1.0f - fy);
            const float w01 = (1.0f - fx) * fy;
            const float w11 = fx * fy;
            const int base = oi * 10 + oj;
            const float val = w00 * dots[px][base] + w10 * dots[px][base + 1] +
                              w01 * dots[px][base + 10] + w11 * dots[px][base + 11];
            out[(size_t)(b * 324 + lvl * 81 + k) * 4096 + hw + px] = val * 0.0625f;
        }
        __syncthreads();
    }
}

// ---------------------------------------------------------------------------
// Inputs: fmap1, fmap2_0..3, coords. Output [2,324,64,64] fp32.
// ---------------------------------------------------------------------------
extern "C" void kernel_launch(void* const* d_in, const int* in_sizes, int n_in,
                              void* d_out, int out_size) {
    const float* f1 = (const float*)d_in[0];
    const float* f2_0 = (const float*)d_in[1];
    const float* f2_1 = (const float*)d_in[2];
    const float* f2_2 = (const float*)d_in[3];
    const float* f2_3 = (const float*)d_in[4];
    const float* coords = (const float*)d_in[5];
    float* out = (float*)d_out;

    static bool attr_done = false;
    if (!attr_done) {
        cudaFuncSetAttribute(gemm_kernel, cudaFuncAttributeMaxDynamicSharedMemorySize,
                             GEMM_SMEM);
        attr_done = true;
    }

    dim3 tb(32, 8);
    tconv_kernel<<<dim3(128, 8, 2), tb>>>(f1, F1H_OFF, (size_t)1048576, 4096);
    tconv_kernel<<<dim3(128, 8, 2), tb>>>(f2_0, F2H_OFF + (size_t)0 * 256, F2_BSTRIDE, 4096);
    tconv_kernel<<<dim3(32, 8, 2), tb>>>(f2_1, F2H_OFF + (size_t)4096 * 256, F2_BSTRIDE, 1024);
    tconv_kernel<<<dim3(8, 8, 2), tb>>>(f2_2, F2H_OFF + (size_t)5120 * 256, F2_BSTRIDE, 256);
    tconv_kernel<<<dim3(2, 8, 2), tb>>>(f2_3, F2H_OFF + (size_t)5376 * 256, F2_BSTRIDE, 64);

    gemm_kernel<<<dim3(43, 32, 2), 256, GEMM_SMEM>>>();

    gather_kernel<<<1024, 256>>>(coords, out);
}

// round 4
// speedup vs baseline: 4.4984x; 1.9737x over previous
#include <cuda_runtime.h>
#include <cuda_fp16.h>
#include <cstdint>
#include <cstddef>

// ---------------------------------------------------------------------------
// Scratch:
//   g_fh: f1h [2][4096][256] fp16 at 0; f2h [2][5504][256] fp16 at 2,097,152
//         (f2 level row bases 0,4096,5120,5376; rows 5440..5503 stay zero —
//          device globals are zero-initialized and never written there)
//   g_corrh: [2][4096][5504] fp16 correlation volume
//   g_mask: per (b, m-tile) bitmask of needed n-tiles (43 bits used)
// ---------------------------------------------------------------------------
#define F1H_OFF ((size_t)0)
#define F2H_OFF ((size_t)2097152)
#define F2_BSTRIDE ((size_t)1409024)   // 5504*256
#define CORR_COLS 5504
__device__ __half g_fh[4915200];
__device__ __half g_corrh[45088768];
__device__ unsigned long long g_mask[64];

__device__ __forceinline__ uint32_t smem_u32(const void* p) {
    uint32_t a;
    asm("{ .reg .u64 t; cvta.to.shared.u64 t, %1; cvt.u32.u64 %0, t; }"
        : "=r"(a) : "l"(p));
    return a;
}

// ---------------------------------------------------------------------------
// Needed-tile mask. One thread per pixel; warp-OR reduce then atomicOr.
// ---------------------------------------------------------------------------
__global__ void mask_init_kernel() { g_mask[threadIdx.x] = 0ULL; }

__global__ __launch_bounds__(256) void mask_kernel(const float* __restrict__ coords) {
    const int idx = blockIdx.x * 256 + threadIdx.x;   // 0..8191
    const int b = idx >> 12, hw = idx & 4095;
    const float x = coords[(size_t)b * 8192 + hw];
    const float y = coords[(size_t)b * 8192 + 4096 + hw];
    const int lb[4] = {0, 4096, 5120, 5376};
    unsigned long long m = 0ULL;
#pragma unroll
    for (int l = 0; l < 4; l++) {
        const int W2 = 64 >> l;
        const float s = 1.0f / (float)(1 << l);
        const int x0 = (int)floorf(x * s);
        const int y0 = (int)floorf(y * s);
        const int gx0 = max(x0 - 4, 0), gx1 = min(x0 + 5, W2 - 1);
        const int gy0 = max(y0 - 4, 0), gy1 = min(y0 + 5, W2 - 1);
        if (gx0 > gx1 || gy0 > gy1) continue;
        const int t0 = (lb[l] + gy0 * W2 + gx0) >> 7;
        const int t1 = (lb[l] + gy1 * W2 + gx1) >> 7;
        m |= (((1ULL << (t1 - t0 + 1)) - 1ULL) << t0);
    }
    unsigned lo = (unsigned)m, hi = (unsigned)(m >> 32);
#pragma unroll
    for (int o = 16; o; o >>= 1) {
        lo |= __shfl_xor_sync(0xffffffffu, lo, o);
        hi |= __shfl_xor_sync(0xffffffffu, hi, o);
    }
    if ((threadIdx.x & 31) == 0)
        atomicOr(&g_mask[b * 32 + (hw >> 7)], ((unsigned long long)hi << 32) | lo);
}

// ---------------------------------------------------------------------------
// Fused transpose+convert: all 5 tensors in one launch.
// grid.x = virtual 32-pixel tile over concatenated segments, grid.y = c-tile,
// grid.z = batch.
// ---------------------------------------------------------------------------
__global__ void tconv_kernel(const float* __restrict__ f1, const float* __restrict__ f20,
                             const float* __restrict__ f21, const float* __restrict__ f22,
                             const float* __restrict__ f23) {
    __shared__ float tile[32][33];
    const int bx = blockIdx.x, bz = blockIdx.z;
    // segments (in 32-px blocks): f1 [0,128), f2_0 [128,256), f2_1 [256,288),
    // f2_2 [288,296), f2_3 [296,298)
    const float* src;
    int P, pBase;
    size_t dstOff, bStride;
    if (bx < 128)      { src = f1;  P = 4096; pBase = bx;            dstOff = F1H_OFF;                         bStride = 1048576; }
    else if (bx < 256) { src = f20; P = 4096; pBase = bx - 128;      dstOff = F2H_OFF;                         bStride = F2_BSTRIDE; }
    else if (bx < 288) { src = f21; P = 1024; pBase = bx - 256;      dstOff = F2H_OFF + (size_t)4096 * 256;    bStride = F2_BSTRIDE; }
    else if (bx < 296) { src = f22; P = 256;  pBase = bx - 288;      dstOff = F2H_OFF + (size_t)5120 * 256;    bStride = F2_BSTRIDE; }
    else               { src = f23; P = 64;   pBase = bx - 296;      dstOff = F2H_OFF + (size_t)5376 * 256;    bStride = F2_BSTRIDE; }

    const float* s = src + (size_t)bz * 256 * P;
    __half* d = g_fh + dstOff + (size_t)bz * bStride;
    const int p0 = pBase * 32, c0 = blockIdx.y * 32;
    const int tx = threadIdx.x, ty = threadIdx.y;
#pragma unroll
    for (int k = 0; k < 4; k++)
        tile[ty + 8 * k][tx] = s[(size_t)(c0 + ty + 8 * k) * P + p0 + tx];
    __syncthreads();
#pragma unroll
    for (int k = 0; k < 4; k++)
        d[(size_t)(p0 + ty + 8 * k) * 256 + c0 + tx] = __float2half(tile[tx][ty + 8 * k]);
}

// ---------------------------------------------------------------------------
// GEMM via mma.sync m16n8k16. Tile 128x128, K=256 in smem. 8 warps (4M x 2N),
// warp tile 32x64. Skips n-tiles not in the needed mask. fp16 output.
// ---------------------------------------------------------------------------
#define AROW 264
#define GEMM_SMEM (2 * 128 * AROW * 2)   // 135168 bytes

__device__ __forceinline__ void ldsm_x4(uint32_t (&r)[4], uint32_t addr) {
    asm volatile("ldmatrix.sync.aligned.m8n8.x4.shared.b16 {%0,%1,%2,%3}, [%4];"
                 : "=r"(r[0]), "=r"(r[1]), "=r"(r[2]), "=r"(r[3]) : "r"(addr));
}
__device__ __forceinline__ void mma16816(float (&d)[4], const uint32_t (&a)[4],
                                         uint32_t b0, uint32_t b1) {
    asm volatile(
        "mma.sync.aligned.m16n8k16.row.col.f32.f16.f16.f32 "
        "{%0,%1,%2,%3},{%4,%5,%6,%7},{%8,%9},{%0,%1,%2,%3};"
        : "+f"(d[0]), "+f"(d[1]), "+f"(d[2]), "+f"(d[3])
        : "r"(a[0]), "r"(a[1]), "r"(a[2]), "r"(a[3]), "r"(b0), "r"(b1));
}

__global__ void __launch_bounds__(256, 1) gemm_kernel() {
    const int nt = blockIdx.x, mt = blockIdx.y, b = blockIdx.z;
    if (!((g_mask[b * 32 + mt] >> nt) & 1ULL)) return;

    extern __shared__ __half sm[];
    __half* sA = sm;
    __half* sB = sm + 128 * AROW;

    const int tid = threadIdx.x, warp = tid >> 5, lane = tid & 31;

    const __half* A = g_fh + F1H_OFF + ((size_t)b * 4096 + (size_t)mt * 128) * 256;
    const __half* B = g_fh + F2H_OFF + (size_t)b * F2_BSTRIDE + (size_t)nt * 128 * 256;

#pragma unroll
    for (int i = tid; i < 4096; i += 256) {
        const int r = i >> 5, c = i & 31;
        *(uint4*)&sA[r * AROW + c * 8] = *(const uint4*)(A + (size_t)r * 256 + c * 8);
        *(uint4*)&sB[r * AROW + c * 8] = *(const uint4*)(B + (size_t)r * 256 + c * 8);
    }
    __syncthreads();

    const int wm = (warp & 3) * 32;
    const int wn = (warp >> 2) * 64;
    const int row_in = lane & 7;
    const int mat = lane >> 3;

    float acc[2][8][4];
#pragma unroll
    for (int mi = 0; mi < 2; mi++)
#pragma unroll
        for (int ni = 0; ni < 8; ni++)
#pragma unroll
            for (int j = 0; j < 4; j++) acc[mi][ni][j] = 0.0f;

    const uint32_t sA0 = smem_u32(sA);
    const uint32_t sB0 = smem_u32(sB);

#pragma unroll 4
    for (int kk = 0; kk < 256; kk += 16) {
        uint32_t af[2][4];
#pragma unroll
        for (int mi = 0; mi < 2; mi++) {
            const int row = wm + mi * 16 + (mat & 1) * 8 + row_in;
            const int col = kk + (mat >> 1) * 8;
            ldsm_x4(af[mi], sA0 + (uint32_t)(row * AROW + col) * 2);
        }
        uint32_t bf[4][4];
#pragma unroll
        for (int bi = 0; bi < 4; bi++) {
            const int nrow = wn + bi * 16 + (mat >> 1) * 8 + row_in;
            const int col = kk + (mat & 1) * 8;
            ldsm_x4(bf[bi], sB0 + (uint32_t)(nrow * AROW + col) * 2);
        }
#pragma unroll
        for (int mi = 0; mi < 2; mi++)
#pragma unroll
            for (int ni = 0; ni < 8; ni++) {
                const uint32_t* bb = bf[ni >> 1];
                if (ni & 1) mma16816(acc[mi][ni], af[mi], bb[2], bb[3]);
                else        mma16816(acc[mi][ni], af[mi], bb[0], bb[1]);
            }
    }

    const int g = lane >> 2, tg = lane & 3;
    __half* crow = g_corrh + ((size_t)b * 4096 + (size_t)mt * 128) * CORR_COLS +
                   (size_t)nt * 128;
#pragma unroll
    for (int mi = 0; mi < 2; mi++) {
#pragma unroll
        for (int ni = 0; ni < 8; ni++) {
            const int rm = wm + mi * 16 + g;
            const int cn = wn + ni * 8 + tg * 2;
            *(__half2*)(crow + (size_t)rm * CORR_COLS + cn) =
                __floats2half2_rn(acc[mi][ni][0], acc[mi][ni][1]);
            *(__half2*)(crow + (size_t)(rm + 8) * CORR_COLS + cn) =
                __floats2half2_rn(acc[mi][ni][2], acc[mi][ni][3]);
        }
    }
}

// ---------------------------------------------------------------------------
// Gather: per (pixel, level) read the 10x10 grid (fp16), bilinear-combine
// into 81 outputs. One block = 8 consecutive pixels.
// ---------------------------------------------------------------------------
__global__ __launch_bounds__(256) void gather_kernel(const float* __restrict__ coords,
                                                     float* __restrict__ out) {
    __shared__ float dots[8][100];
    __shared__ float s_cx[8], s_cy[8];

    const int tid = threadIdx.x;
    const int pix0 = blockIdx.x * 8;
    const int b = pix0 >> 12;
    const int hw = pix0 & 4095;

    if (tid < 8) {
        s_cx[tid] = coords[(size_t)b * 8192 + hw + tid];
        s_cy[tid] = coords[(size_t)b * 8192 + 4096 + hw + tid];
    }
    __syncthreads();

    const int lvl_base[4] = {0, 4096, 5120, 5376};

#pragma unroll 1
    for (int lvl = 0; lvl < 4; lvl++) {
        const int W2 = 64 >> lvl;
        const float scale = 1.0f / (float)(1 << lvl);
        const int lb = lvl_base[lvl];

        for (int e = tid; e < 1024; e += 256) {
            const int px = e >> 7;
            const int pt = e & 127;
            if (pt < 100) {
                const float x = s_cx[px] * scale;
                const float y = s_cy[px] * scale;
                const int x0 = (int)floorf(x);
                const int y0 = (int)floorf(y);
                const int gi = pt / 10;
                const int gj = pt - gi * 10;
                const int gx = x0 - 4 + gj;
                const int gy = y0 - 4 + gi;
                float v = 0.0f;
                if ((unsigned)gx < (unsigned)W2 && (unsigned)gy < (unsigned)W2)
                    v = __half2float(
                        g_corrh[((size_t)b * 4096 + hw + px) * CORR_COLS + lb + gy * W2 + gx]);
                dots[px][pt] = v;
            }
        }
        __syncthreads();

        for (int e = tid; e < 648; e += 256) {
            const int k = e >> 3;
            const int px = e & 7;
            const int oi = k / 9;
            const int oj = k - oi * 9;
            const float x = s_cx[px] * scale;
            const float y = s_cy[px] * scale;
            const float fx = x - floorf(x);
            const float fy = y - floorf(y);
            const float w00 = (1.0f - fx) * (1.0f - fy);
            const float w10 = fx * (1.0f - fy);
            const float w01 = (1.0f - fx) * fy;
            const float w11 = fx * fy;
            const int base = oi * 10 + oj;
            const float val = w00 * dots[px][base] + w10 * dots[px][base + 1] +
                              w01 * dots[px][base + 10] + w11 * dots[px][base + 11];
            out[(size_t)(b * 324 + lvl * 81 + k) * 4096 + hw + px] = val * 0.0625f;
        }
        __syncthreads();
    }
}

// ---------------------------------------------------------------------------
// Inputs: fmap1, fmap2_0..3, coords. Output [2,324,64,64] fp32.
// ---------------------------------------------------------------------------
extern "C" void kernel_launch(void* const* d_in, const int* in_sizes, int n_in,
                              void* d_out, int out_size) {
    const float* f1 = (const float*)d_in[0];
    const float* f2_0 = (const float*)d_in[1];
    const float* f2_1 = (const float*)d_in[2];
    const float* f2_2 = (const float*)d_in[3];
    const float* f2_3 = (const float*)d_in[4];
    const float* coords = (const float*)d_in[5];
    float* out = (float*)d_out;

    static bool attr_done = false;
    if (!attr_done) {
        cudaFuncSetAttribute(gemm_kernel, cudaFuncAttributeMaxDynamicSharedMemorySize,
                             GEMM_SMEM);
        attr_done = true;
    }

    mask_init_kernel<<<1, 64>>>();
    mask_kernel<<<32, 256>>>(coords);
    tconv_kernel<<<dim3(298, 8, 2), dim3(32, 8)>>>(f1, f2_0, f2_1, f2_2, f2_3);
    gemm_kernel<<<dim3(43, 32, 2), 256, GEMM_SMEM>>>();
    gather_kernel<<<1024, 256>>>(coords, out);
}

// round 5
// speedup vs baseline: 5.6247x; 1.2504x over previous
#include <cuda_runtime.h>
#include <cuda_fp16.h>
#include <cstdint>
#include <cstddef>

// ---------------------------------------------------------------------------
// Scratch:
//   g_fh: f1h [2][4096][256] fp16 at 0; f2h [2][5504][256] fp16 at 2,097,152
//         (f2 level row bases 0,4096,5120,5376; rows 5440..5503 stay zero)
//   g_corrh: [2][4096][5504] fp16 correlation volume
//   g_mask: per (b, m-tile) bitmask of needed n-tiles (43 bits used)
// ---------------------------------------------------------------------------
#define F1H_OFF ((size_t)0)
#define F2H_OFF ((size_t)2097152)
#define F2_BSTRIDE ((size_t)1409024)   // 5504*256
#define CORR_COLS 5504
__device__ __half g_fh[4915200];
__device__ __half g_corrh[45088768];
__device__ unsigned long long g_mask[64];

__device__ __forceinline__ uint32_t smem_u32(const void* p) {
    uint32_t a;
    asm("{ .reg .u64 t; cvta.to.shared.u64 t, %1; cvt.u32.u64 %0, t; }"
        : "=r"(a) : "l"(p));
    return a;
}

// ---------------------------------------------------------------------------
// Needed-tile mask
// ---------------------------------------------------------------------------
__global__ void mask_init_kernel() { g_mask[threadIdx.x] = 0ULL; }

__global__ __launch_bounds__(256) void mask_kernel(const float* __restrict__ coords) {
    const int idx = blockIdx.x * 256 + threadIdx.x;
    const int b = idx >> 12, hw = idx & 4095;
    const float x = coords[(size_t)b * 8192 + hw];
    const float y = coords[(size_t)b * 8192 + 4096 + hw];
    const int lb[4] = {0, 4096, 5120, 5376};
    unsigned long long m = 0ULL;
#pragma unroll
    for (int l = 0; l < 4; l++) {
        const int W2 = 64 >> l;
        const float s = 1.0f / (float)(1 << l);
        const int x0 = (int)floorf(x * s);
        const int y0 = (int)floorf(y * s);
        const int gx0 = max(x0 - 4, 0), gx1 = min(x0 + 5, W2 - 1);
        const int gy0 = max(y0 - 4, 0), gy1 = min(y0 + 5, W2 - 1);
        if (gx0 > gx1 || gy0 > gy1) continue;
        const int t0 = (lb[l] + gy0 * W2 + gx0) >> 7;
        const int t1 = (lb[l] + gy1 * W2 + gx1) >> 7;
        m |= (((1ULL << (t1 - t0 + 1)) - 1ULL) << t0);
    }
    unsigned lo = (unsigned)m, hi = (unsigned)(m >> 32);
#pragma unroll
    for (int o = 16; o; o >>= 1) {
        lo |= __shfl_xor_sync(0xffffffffu, lo, o);
        hi |= __shfl_xor_sync(0xffffffffu, hi, o);
    }
    if ((threadIdx.x & 31) == 0)
        atomicOr(&g_mask[b * 32 + (hw >> 7)], ((unsigned long long)hi << 32) | lo);
}

// ---------------------------------------------------------------------------
// Fused transpose+convert
// ---------------------------------------------------------------------------
__global__ void tconv_kernel(const float* __restrict__ f1, const float* __restrict__ f20,
                             const float* __restrict__ f21, const float* __restrict__ f22,
                             const float* __restrict__ f23) {
    __shared__ float tile[32][33];
    const int bx = blockIdx.x, bz = blockIdx.z;
    const float* src;
    int P, pBase;
    size_t dstOff, bStride;
    if (bx < 128)      { src = f1;  P = 4096; pBase = bx;       dstOff = F1H_OFF;                      bStride = 1048576; }
    else if (bx < 256) { src = f20; P = 4096; pBase = bx - 128; dstOff = F2H_OFF;                      bStride = F2_BSTRIDE; }
    else if (bx < 288) { src = f21; P = 1024; pBase = bx - 256; dstOff = F2H_OFF + (size_t)4096 * 256; bStride = F2_BSTRIDE; }
    else if (bx < 296) { src = f22; P = 256;  pBase = bx - 288; dstOff = F2H_OFF + (size_t)5120 * 256; bStride = F2_BSTRIDE; }
    else               { src = f23; P = 64;   pBase = bx - 296; dstOff = F2H_OFF + (size_t)5376 * 256; bStride = F2_BSTRIDE; }

    const float* s = src + (size_t)bz * 256 * P;
    __half* d = g_fh + dstOff + (size_t)bz * bStride;
    const int p0 = pBase * 32, c0 = blockIdx.y * 32;
    const int tx = threadIdx.x, ty = threadIdx.y;
#pragma unroll
    for (int k = 0; k < 4; k++)
        tile[ty + 8 * k][tx] = s[(size_t)(c0 + ty + 8 * k) * P + p0 + tx];
    __syncthreads();
#pragma unroll
    for (int k = 0; k < 4; k++)
        d[(size_t)(p0 + ty + 8 * k) * 256 + c0 + tx] = __float2half(tile[tx][ty + 8 * k]);
}

// ---------------------------------------------------------------------------
// GEMM: 128x128 tile, K=256 in 4 chunks of 64, cp.async 3-stage pipeline.
// 8 warps (4M x 2N), warp tile 32x64. 96KB smem -> 2 CTAs/SM.
// Smem tile: 128 rows x 64 halves (128B row); 16B chunk c of row r stored at
// chunk (c ^ (r&7))  -> conflict-free for cp.async stores and ldmatrix reads.
// ---------------------------------------------------------------------------
#define STAGE_BYTES 32768
#define GEMM_SMEM   (3 * STAGE_BYTES)   // 98304

__device__ __forceinline__ void ldsm_x4(uint32_t (&r)[4], uint32_t addr) {
    asm volatile("ldmatrix.sync.aligned.m8n8.x4.shared.b16 {%0,%1,%2,%3}, [%4];"
                 : "=r"(r[0]), "=r"(r[1]), "=r"(r[2]), "=r"(r[3]) : "r"(addr));
}
__device__ __forceinline__ void mma16816(float (&d)[4], const uint32_t (&a)[4],
                                         uint32_t b0, uint32_t b1) {
    asm volatile(
        "mma.sync.aligned.m16n8k16.row.col.f32.f16.f16.f32 "
        "{%0,%1,%2,%3},{%4,%5,%6,%7},{%8,%9},{%0,%1,%2,%3};"
        : "+f"(d[0]), "+f"(d[1]), "+f"(d[2]), "+f"(d[3])
        : "r"(a[0]), "r"(a[1]), "r"(a[2]), "r"(a[3]), "r"(b0), "r"(b1));
}

__device__ __forceinline__ uint32_t sw_addr(uint32_t base, int row, int chunk) {
    return base + (uint32_t)row * 128u + (uint32_t)((chunk ^ (row & 7)) << 4);
}

__device__ __forceinline__ void load_chunk(const __half* __restrict__ A,
                                           const __half* __restrict__ B,
                                           uint32_t sbase, int stage, int ck, int tid) {
    const uint32_t aoff = sbase + stage * STAGE_BYTES;
    const uint32_t boff = aoff + 16384;
#pragma unroll
    for (int q = tid; q < 1024; q += 256) {
        const int r = q >> 3, c = q & 7;
        const uint32_t sa = sw_addr(aoff, r, c);
        const uint32_t sb = sw_addr(boff, r, c);
        const __half* ga = A + (size_t)r * 256 + ck * 64 + c * 8;
        const __half* gb = B + (size_t)r * 256 + ck * 64 + c * 8;
        asm volatile("cp.async.cg.shared.global [%0], [%1], 16;" :: "r"(sa), "l"(ga));
        asm volatile("cp.async.cg.shared.global [%0], [%1], 16;" :: "r"(sb), "l"(gb));
    }
    asm volatile("cp.async.commit_group;" ::: "memory");
}

__global__ void __launch_bounds__(256, 2) gemm_kernel() {
    const int nt = blockIdx.x, mt = blockIdx.y, b = blockIdx.z;
    if (!((g_mask[b * 32 + mt] >> nt) & 1ULL)) return;

    extern __shared__ char smraw[];
    const uint32_t sbase = smem_u32(smraw);
    const int tid = threadIdx.x, warp = tid >> 5, lane = tid & 31;

    const __half* A = g_fh + F1H_OFF + ((size_t)b * 4096 + (size_t)mt * 128) * 256;
    const __half* B = g_fh + F2H_OFF + (size_t)b * F2_BSTRIDE + (size_t)nt * 128 * 256;

    load_chunk(A, B, sbase, 0, 0, tid);
    load_chunk(A, B, sbase, 1, 1, tid);

    const int wm = (warp & 3) * 32;
    const int wn = (warp >> 2) * 64;
    const int row_in = lane & 7;
    const int mat = lane >> 3;

    float acc[2][8][4];
#pragma unroll
    for (int mi = 0; mi < 2; mi++)
#pragma unroll
        for (int ni = 0; ni < 8; ni++)
#pragma unroll
            for (int j = 0; j < 4; j++) acc[mi][ni][j] = 0.0f;

#pragma unroll
    for (int ck = 0; ck < 4; ck++) {
        if (ck < 3) asm volatile("cp.async.wait_group 1;" ::: "memory");
        else        asm volatile("cp.async.wait_group 0;" ::: "memory");
        __syncthreads();
        if (ck + 2 < 4) load_chunk(A, B, sbase, (ck + 2) % 3, ck + 2, tid);

        const uint32_t aT = sbase + (ck % 3) * STAGE_BYTES;
        const uint32_t bT = aT + 16384;

#pragma unroll
        for (int ks = 0; ks < 4; ks++) {      // 4 k-steps of 16 within chunk
            uint32_t af[2][4];
#pragma unroll
            for (int mi = 0; mi < 2; mi++) {
                const int row = wm + mi * 16 + (mat & 1) * 8 + row_in;
                const int chunk = ks * 2 + (mat >> 1);
                ldsm_x4(af[mi], sw_addr(aT, row, chunk));
            }
            uint32_t bf[4][4];
#pragma unroll
            for (int bi = 0; bi < 4; bi++) {
                const int nrow = wn + bi * 16 + (mat >> 1) * 8 + row_in;
                const int chunk = ks * 2 + (mat & 1);
                ldsm_x4(bf[bi], sw_addr(bT, nrow, chunk));
            }
#pragma unroll
            for (int mi = 0; mi < 2; mi++)
#pragma unroll
                for (int ni = 0; ni < 8; ni++) {
                    const uint32_t* bb = bf[ni >> 1];
                    if (ni & 1) mma16816(acc[mi][ni], af[mi], bb[2], bb[3]);
                    else        mma16816(acc[mi][ni], af[mi], bb[0], bb[1]);
                }
        }
        __syncthreads();
    }

    const int g = lane >> 2, tg = lane & 3;
    __half* crow = g_corrh + ((size_t)b * 4096 + (size_t)mt * 128) * CORR_COLS +
                   (size_t)nt * 128;
#pragma unroll
    for (int mi = 0; mi < 2; mi++) {
#pragma unroll
        for (int ni = 0; ni < 8; ni++) {
            const int rm = wm + mi * 16 + g;
            const int cn = wn + ni * 8 + tg * 2;
            *(__half2*)(crow + (size_t)rm * CORR_COLS + cn) =
                __floats2half2_rn(acc[mi][ni][0], acc[mi][ni][1]);
            *(__half2*)(crow + (size_t)(rm + 8) * CORR_COLS + cn) =
                __floats2half2_rn(acc[mi][ni][2], acc[mi][ni][3]);
        }
    }
}

// ---------------------------------------------------------------------------
// Gather
// ---------------------------------------------------------------------------
__global__ __launch_bounds__(256) void gather_kernel(const float* __restrict__ coords,
                                                     float* __restrict__ out) {
    __shared__ float dots[8][100];
    __shared__ float s_cx[8], s_cy[8];

    const int tid = threadIdx.x;
    const int pix0 = blockIdx.x * 8;
    const int b = pix0 >> 12;
    const int hw = pix0 & 4095;

    if (tid < 8) {
        s_cx[tid] = coords[(size_t)b * 8192 + hw + tid];
        s_cy[tid] = coords[(size_t)b * 8192 + 4096 + hw + tid];
    }
    __syncthreads();

    const int lvl_base[4] = {0, 4096, 5120, 5376};

#pragma unroll 1
    for (int lvl = 0; lvl < 4; lvl++) {
        const int W2 = 64 >> lvl;
        const float scale = 1.0f / (float)(1 << lvl);
        const int lb = lvl_base[lvl];

        for (int e = tid; e < 1024; e += 256) {
            const int px = e >> 7;
            const int pt = e & 127;
            if (pt < 100) {
                const float x = s_cx[px] * scale;
                const float y = s_cy[px] * scale;
                const int x0 = (int)floorf(x);
                const int y0 = (int)floorf(y);
                const int gi = pt / 10;
                const int gj = pt - gi * 10;
                const int gx = x0 - 4 + gj;
                const int gy = y0 - 4 + gi;
                float v = 0.0f;
                if ((unsigned)gx < (unsigned)W2 && (unsigned)gy < (unsigned)W2)
                    v = __half2float(
                        g_corrh[((size_t)b * 4096 + hw + px) * CORR_COLS + lb + gy * W2 + gx]);
                dots[px][pt] = v;
            }
        }
        __syncthreads();

        for (int e = tid; e < 648; e += 256) {
            const int k = e >> 3;
            const int px = e & 7;
            const int oi = k / 9;
            const int oj = k - oi * 9;
            const float x = s_cx[px] * scale;
            const float y = s_cy[px] * scale;
            const float fx = x - floorf(x);
            const float fy = y - floorf(y);
            const float w00 = (1.0f - fx) * (1.0f - fy);
            const float w10 = fx * (1.0f - fy);
            const float w01 = (1.0f - fx) * fy;
            const float w11 = fx * fy;
            const int base = oi * 10 + oj;
            const float val = w00 * dots[px][base] + w10 * dots[px][base + 1] +
                              w01 * dots[px][base + 10] + w11 * dots[px][base + 11];
            out[(size_t)(b * 324 + lvl * 81 + k) * 4096 + hw + px] = val * 0.0625f;
        }
        __syncthreads();
    }
}

// ---------------------------------------------------------------------------
// Inputs: fmap1, fmap2_0..3, coords. Output [2,324,64,64] fp32.
// ---------------------------------------------------------------------------
extern "C" void kernel_launch(void* const* d_in, const int* in_sizes, int n_in,
                              void* d_out, int out_size) {
    const float* f1 = (const float*)d_in[0];
    const float* f2_0 = (const float*)d_in[1];
    const float* f2_1 = (const float*)d_in[2];
    const float* f2_2 = (const float*)d_in[3];
    const float* f2_3 = (const float*)d_in[4];
    const float* coords = (const float*)d_in[5];
    float* out = (float*)d_out;

    static bool attr_done = false;
    if (!attr_done) {
        cudaFuncSetAttribute(gemm_kernel, cudaFuncAttributeMaxDynamicSharedMemorySize,
                             GEMM_SMEM);
        attr_done = true;
    }

    mask_init_kernel<<<1, 64>>>();
    mask_kernel<<<32, 256>>>(coords);
    tconv_kernel<<<dim3(298, 8, 2), dim3(32, 8)>>>(f1, f2_0, f2_1, f2_2, f2_3);
    gemm_kernel<<<dim3(43, 32, 2), 256, GEMM_SMEM>>>();
    gather_kernel<<<1024, 256>>>(coords, out);
}

// round 6
// speedup vs baseline: 5.9039x; 1.0496x over previous
#include <cuda_runtime.h>
#include <cuda_fp16.h>
#include <cstdint>
#include <cstddef>

// ---------------------------------------------------------------------------
// Scratch:
//   g_fh: f1h [2][4096][256] fp16 at 0; f2h [2][5504][256] fp16 at 2,097,152
//         (f2 level row bases 0,4096,5120,5376; rows 5440..5503 stay zero)
//   g_corrh: [2][4096][5504] fp16 correlation volume
//   g_mask: per (b, m-tile) bitmask of needed n-tiles (43 bits used)
// ---------------------------------------------------------------------------
#define F1H_OFF ((size_t)0)
#define F2H_OFF ((size_t)2097152)
#define F2_BSTRIDE ((size_t)1409024)   // 5504*256
#define CORR_COLS 5504
__device__ __half g_fh[4915200];
__device__ __half g_corrh[45088768];
__device__ unsigned long long g_mask[64];

__device__ __forceinline__ uint32_t smem_u32(const void* p) {
    uint32_t a;
    asm("{ .reg .u64 t; cvta.to.shared.u64 t, %1; cvt.u32.u64 %0, t; }"
        : "=r"(a) : "l"(p));
    return a;
}

// ---------------------------------------------------------------------------
// Fused transpose+convert + needed-tile mask.
// bx < 298: tconv segments. bx in [298, 306) with by==0, bz==0: mask blocks
// (8 blocks x 8 warps = 64 warps; warp w -> (b, mtile), no atomics needed).
// ---------------------------------------------------------------------------
__global__ void tconv_kernel(const float* __restrict__ f1, const float* __restrict__ f20,
                             const float* __restrict__ f21, const float* __restrict__ f22,
                             const float* __restrict__ f23,
                             const float* __restrict__ coords) {
    __shared__ float tile[32][33];
    const int bx = blockIdx.x, bz = blockIdx.z;
    const int tx = threadIdx.x, ty = threadIdx.y;

    if (bx >= 298) {
        if (blockIdx.y != 0 || bz != 0) return;
        const int tid = ty * 32 + tx;
        const int gw = (bx - 298) * 8 + (tid >> 5);   // 0..63
        const int lane = tid & 31;
        const int b = gw >> 5, mt = gw & 31;
        const int lb[4] = {0, 4096, 5120, 5376};
        unsigned long long m = 0ULL;
#pragma unroll
        for (int j = 0; j < 4; j++) {
            const int hw = mt * 128 + j * 32 + lane;
            const float x = coords[(size_t)b * 8192 + hw];
            const float y = coords[(size_t)b * 8192 + 4096 + hw];
#pragma unroll
            for (int l = 0; l < 4; l++) {
                const int W2 = 64 >> l;
                const float s = 1.0f / (float)(1 << l);
                const int x0 = (int)floorf(x * s);
                const int y0 = (int)floorf(y * s);
                const int gx0 = max(x0 - 4, 0), gx1 = min(x0 + 5, W2 - 1);
                const int gy0 = max(y0 - 4, 0), gy1 = min(y0 + 5, W2 - 1);
                if (gx0 > gx1 || gy0 > gy1) continue;
                const int t0 = (lb[l] + gy0 * W2 + gx0) >> 7;
                const int t1 = (lb[l] + gy1 * W2 + gx1) >> 7;
                m |= (((1ULL << (t1 - t0 + 1)) - 1ULL) << t0);
            }
        }
        unsigned lo = (unsigned)m, hi = (unsigned)(m >> 32);
#pragma unroll
        for (int o = 16; o; o >>= 1) {
            lo |= __shfl_xor_sync(0xffffffffu, lo, o);
            hi |= __shfl_xor_sync(0xffffffffu, hi, o);
        }
        if (lane == 0) g_mask[gw] = ((unsigned long long)hi << 32) | lo;
        return;
    }

    const float* src;
    int P, pBase;
    size_t dstOff, bStride;
    if (bx < 128)      { src = f1;  P = 4096; pBase = bx;       dstOff = F1H_OFF;                      bStride = 1048576; }
    else if (bx < 256) { src = f20; P = 4096; pBase = bx - 128; dstOff = F2H_OFF;                      bStride = F2_BSTRIDE; }
    else if (bx < 288) { src = f21; P = 1024; pBase = bx - 256; dstOff = F2H_OFF + (size_t)4096 * 256; bStride = F2_BSTRIDE; }
    else if (bx < 296) { src = f22; P = 256;  pBase = bx - 288; dstOff = F2H_OFF + (size_t)5120 * 256; bStride = F2_BSTRIDE; }
    else               { src = f23; P = 64;   pBase = bx - 296; dstOff = F2H_OFF + (size_t)5376 * 256; bStride = F2_BSTRIDE; }

    const float* s = src + (size_t)bz * 256 * P;
    __half* d = g_fh + dstOff + (size_t)bz * bStride;
    const int p0 = pBase * 32, c0 = blockIdx.y * 32;
#pragma unroll
    for (int k = 0; k < 4; k++)
        tile[ty + 8 * k][tx] = s[(size_t)(c0 + ty + 8 * k) * P + p0 + tx];
    __syncthreads();
#pragma unroll
    for (int k = 0; k < 4; k++)
        d[(size_t)(p0 + ty + 8 * k) * 256 + c0 + tx] = __float2half(tile[tx][ty + 8 * k]);
}

// ---------------------------------------------------------------------------
// GEMM: 128x128 tile, K=256 in 4 chunks of 64, cp.async 3-stage pipeline.
// 128 threads / 4 warps (2M x 2N), warp tile 64x64 -> 256-reg budget, high
// MMA:ldsm ratio, low cross-warp smem redundancy. 96KB smem -> 2 CTAs/SM.
// ---------------------------------------------------------------------------
#define STAGE_BYTES 32768
#define GEMM_SMEM   (3 * STAGE_BYTES)   // 98304

__device__ __forceinline__ void ldsm_x4(uint32_t (&r)[4], uint32_t addr) {
    asm volatile("ldmatrix.sync.aligned.m8n8.x4.shared.b16 {%0,%1,%2,%3}, [%4];"
                 : "=r"(r[0]), "=r"(r[1]), "=r"(r[2]), "=r"(r[3]) : "r"(addr));
}
__device__ __forceinline__ void mma16816(float (&d)[4], const uint32_t (&a)[4],
                                         uint32_t b0, uint32_t b1) {
    asm volatile(
        "mma.sync.aligned.m16n8k16.row.col.f32.f16.f16.f32 "
        "{%0,%1,%2,%3},{%4,%5,%6,%7},{%8,%9},{%0,%1,%2,%3};"
        : "+f"(d[0]), "+f"(d[1]), "+f"(d[2]), "+f"(d[3])
        : "r"(a[0]), "r"(a[1]), "r"(a[2]), "r"(a[3]), "r"(b0), "r"(b1));
}

__device__ __forceinline__ uint32_t sw_addr(uint32_t base, int row, int chunk) {
    return base + (uint32_t)row * 128u + (uint32_t)((chunk ^ (row & 7)) << 4);
}

__device__ __forceinline__ void load_chunk(const __half* __restrict__ A,
                                           const __half* __restrict__ B,
                                           uint32_t sbase, int stage, int ck, int tid) {
    const uint32_t aoff = sbase + stage * STAGE_BYTES;
    const uint32_t boff = aoff + 16384;
#pragma unroll
    for (int q = tid; q < 1024; q += 128) {
        const int r = q >> 3, c = q & 7;
        const uint32_t sa = sw_addr(aoff, r, c);
        const uint32_t sb = sw_addr(boff, r, c);
        const __half* ga = A + (size_t)r * 256 + ck * 64 + c * 8;
        const __half* gb = B + (size_t)r * 256 + ck * 64 + c * 8;
        asm volatile("cp.async.cg.shared.global [%0], [%1], 16;" :: "r"(sa), "l"(ga));
        asm volatile("cp.async.cg.shared.global [%0], [%1], 16;" :: "r"(sb), "l"(gb));
    }
    asm volatile("cp.async.commit_group;" ::: "memory");
}

__global__ void __launch_bounds__(128, 2) gemm_kernel() {
    const int nt = blockIdx.x, mt = blockIdx.y, b = blockIdx.z;
    if (!((g_mask[b * 32 + mt] >> nt) & 1ULL)) return;

    extern __shared__ char smraw[];
    const uint32_t sbase = smem_u32(smraw);
    const int tid = threadIdx.x, warp = tid >> 5, lane = tid & 31;

    const __half* A = g_fh + F1H_OFF + ((size_t)b * 4096 + (size_t)mt * 128) * 256;
    const __half* B = g_fh + F2H_OFF + (size_t)b * F2_BSTRIDE + (size_t)nt * 128 * 256;

    load_chunk(A, B, sbase, 0, 0, tid);
    load_chunk(A, B, sbase, 1, 1, tid);

    const int wm = (warp & 1) * 64;
    const int wn = (warp >> 1) * 64;
    const int row_in = lane & 7;
    const int mat = lane >> 3;

    float acc[4][8][4];
#pragma unroll
    for (int mi = 0; mi < 4; mi++)
#pragma unroll
        for (int ni = 0; ni < 8; ni++)
#pragma unroll
            for (int j = 0; j < 4; j++) acc[mi][ni][j] = 0.0f;

#pragma unroll
    for (int ck = 0; ck < 4; ck++) {
        if (ck < 3) asm volatile("cp.async.wait_group 1;" ::: "memory");
        else        asm volatile("cp.async.wait_group 0;" ::: "memory");
        __syncthreads();
        if (ck + 2 < 4) load_chunk(A, B, sbase, (ck + 2) % 3, ck + 2, tid);

        const uint32_t aT = sbase + (ck % 3) * STAGE_BYTES;
        const uint32_t bT = aT + 16384;

#pragma unroll
        for (int ks = 0; ks < 4; ks++) {      // 4 k-steps of 16 within chunk
            uint32_t af[4][4];
#pragma unroll
            for (int mi = 0; mi < 4; mi++) {
                const int row = wm + mi * 16 + (mat & 1) * 8 + row_in;
                const int chunk = ks * 2 + (mat >> 1);
                ldsm_x4(af[mi], sw_addr(aT, row, chunk));
            }
            uint32_t bf[4][4];
#pragma unroll
            for (int bi = 0; bi < 4; bi++) {
                const int nrow = wn + bi * 16 + (mat >> 1) * 8 + row_in;
                const int chunk = ks * 2 + (mat & 1);
                ldsm_x4(bf[bi], sw_addr(bT, nrow, chunk));
            }
#pragma unroll
            for (int mi = 0; mi < 4; mi++)
#pragma unroll
                for (int ni = 0; ni < 8; ni++) {
                    const uint32_t* bb = bf[ni >> 1];
                    if (ni & 1) mma16816(acc[mi][ni], af[mi], bb[2], bb[3]);
                    else        mma16816(acc[mi][ni], af[mi], bb[0], bb[1]);
                }
        }
    }

    const int g = lane >> 2, tg = lane & 3;
    __half* crow = g_corrh + ((size_t)b * 4096 + (size_t)mt * 128) * CORR_COLS +
                   (size_t)nt * 128;
#pragma unroll
    for (int mi = 0; mi < 4; mi++) {
#pragma unroll
        for (int ni = 0; ni < 8; ni++) {
            const int rm = wm + mi * 16 + g;
            const int cn = wn + ni * 8 + tg * 2;
            *(__half2*)(crow + (size_t)rm * CORR_COLS + cn) =
                __floats2half2_rn(acc[mi][ni][0], acc[mi][ni][1]);
            *(__half2*)(crow + (size_t)(rm + 8) * CORR_COLS + cn) =
                __floats2half2_rn(acc[mi][ni][2], acc[mi][ni][3]);
        }
    }
}

// ---------------------------------------------------------------------------
// Gather
// ---------------------------------------------------------------------------
__global__ __launch_bounds__(256) void gather_kernel(const float* __restrict__ coords,
                                                     float* __restrict__ out) {
    __shared__ float dots[8][100];
    __shared__ float s_cx[8], s_cy[8];

    const int tid = threadIdx.x;
    const int pix0 = blockIdx.x * 8;
    const int b = pix0 >> 12;
    const int hw = pix0 & 4095;

    if (tid < 8) {
        s_cx[tid] = coords[(size_t)b * 8192 + hw + tid];
        s_cy[tid] = coords[(size_t)b * 8192 + 4096 + hw + tid];
    }
    __syncthreads();

    const int lvl_base[4] = {0, 4096, 5120, 5376};

#pragma unroll 1
    for (int lvl = 0; lvl < 4; lvl++) {
        const int W2 = 64 >> lvl;
        const float scale = 1.0f / (float)(1 << lvl);
        const int lb = lvl_base[lvl];

        for (int e = tid; e < 1024; e += 256) {
            const int px = e >> 7;
            const int pt = e & 127;
            if (pt < 100) {
                const float x = s_cx[px] * scale;
                const float y = s_cy[px] * scale;
                const int x0 = (int)floorf(x);
                const int y0 = (int)floorf(y);
                const int gi = pt / 10;
                const int gj = pt - gi * 10;
                const int gx = x0 - 4 + gj;
                const int gy = y0 - 4 + gi;
                float v = 0.0f;
                if ((unsigned)gx < (unsigned)W2 && (unsigned)gy < (unsigned)W2)
                    v = __half2float(
                        g_corrh[((size_t)b * 4096 + hw + px) * CORR_COLS + lb + gy * W2 + gx]);
                dots[px][pt] = v;
            }
        }
        __syncthreads();

        for (int e = tid; e < 648; e += 256) {
            const int k = e >> 3;
            const int px = e & 7;
            const int oi = k / 9;
            const int oj = k - oi * 9;
            const float x = s_cx[px] * scale;
            const float y = s_cy[px] * scale;
            const float fx = x - floorf(x);
            const float fy = y - floorf(y);
            const float w00 = (1.0f - fx) * (1.0f - fy);
            const float w10 = fx * (1.0f - fy);
            const float w01 = (1.0f - fx) * fy;
            const float w11 = fx * fy;
            const int base = oi * 10 + oj;
            const float val = w00 * dots[px][base] + w10 * dots[px][base + 1] +
                              w01 * dots[px][base + 10] + w11 * dots[px][base + 11];
            out[(size_t)(b * 324 + lvl * 81 + k) * 4096 + hw + px] = val * 0.0625f;
        }
        __syncthreads();
    }
}

// ---------------------------------------------------------------------------
// Inputs: fmap1, fmap2_0..3, coords. Output [2,324,64,64] fp32.
// ---------------------------------------------------------------------------
extern "C" void kernel_launch(void* const* d_in, const int* in_sizes, int n_in,
                              void* d_out, int out_size) {
    const float* f1 = (const float*)d_in[0];
    const float* f2_0 = (const float*)d_in[1];
    const float* f2_1 = (const float*)d_in[2];
    const float* f2_2 = (const float*)d_in[3];
    const float* f2_3 = (const float*)d_in[4];
    const float* coords = (const float*)d_in[5];
    float* out = (float*)d_out;

    static bool attr_done = false;
    if (!attr_done) {
        cudaFuncSetAttribute(gemm_kernel, cudaFuncAttributeMaxDynamicSharedMemorySize,
                             GEMM_SMEM);
        attr_done = true;
    }

    tconv_kernel<<<dim3(306, 8, 2), dim3(32, 8)>>>(f1, f2_0, f2_1, f2_2, f2_3, coords);
    gemm_kernel<<<dim3(43, 32, 2), 128, GEMM_SMEM>>>();
    gather_kernel<<<1024, 256>>>(coords, out);
}